// round 7
// baseline (speedup 1.0000x reference)
#include <cuda_runtime.h>

#define NN 512
#define NC 16
#define NK 262144            // 2^18
#define NPIX (NN * NN)
#define XSTR 575             // per-line FFT-exchange stride (float2), layout i+(i>>3)

// gridA: coil-interleaved scatter target: [cg][pix][cl], cg=0,1, cl=0..7.
// gridB: per-coil planes [c][row][col] (row-FFT output, col-FFT input).
__device__ __align__(16) float2 g_bufA[NC * NPIX];
__device__ __align__(16) float2 g_bufB[NC * NPIX];

// ---------------------------------------------------------------------------
// complex helpers
// ---------------------------------------------------------------------------
__device__ __forceinline__ float2 cmul(float2 a, float2 b) {
    return make_float2(fmaf(a.x, b.x, -a.y * b.y), fmaf(a.x, b.y, a.y * b.x));
}
__device__ __forceinline__ float2 cadd(float2 a, float2 b) { return make_float2(a.x + b.x, a.y + b.y); }
__device__ __forceinline__ float2 csub(float2 a, float2 b) { return make_float2(a.x - b.x, a.y - b.y); }
__device__ __forceinline__ float2 muli(float2 a) { return make_float2(-a.y, a.x); }  // * (+i)

// 8-point unnormalized inverse DFT (sign +i), in place.
__device__ __forceinline__ void dft8(float2* x) {
    const float C = 0.70710678118654752440f;
    float2 u0 = cadd(x[0], x[4]);
    float2 u1 = csub(x[0], x[4]);
    float2 u2 = cadd(x[1], x[5]);
    float2 d1 = csub(x[1], x[5]);
    float2 u3 = make_float2(C * (d1.x - d1.y), C * (d1.x + d1.y));
    float2 u4 = cadd(x[2], x[6]);
    float2 u5 = muli(csub(x[2], x[6]));
    float2 u6 = cadd(x[3], x[7]);
    float2 d3 = csub(x[3], x[7]);
    float2 u7 = make_float2(-C * (d3.x + d3.y), C * (d3.x - d3.y));
    float2 v0 = cadd(u0, u4);
    float2 v2 = csub(u0, u4);
    float2 v1 = cadd(u1, u5);
    float2 v3 = csub(u1, u5);
    float2 v4 = cadd(u2, u6);
    float2 v6 = muli(csub(u2, u6));
    float2 v5 = cadd(u3, u7);
    float2 v7 = muli(csub(u3, u7));
    x[0] = cadd(v0, v4);
    x[4] = csub(v0, v4);
    x[1] = cadd(v1, v5);
    x[5] = csub(v1, v5);
    x[2] = cadd(v2, v6);
    x[6] = csub(v2, v6);
    x[3] = cadd(v3, v7);
    x[7] = csub(v3, v7);
}

__device__ __forceinline__ void twiddle7(float2* x, float ang) {
    float2 w;
    __sincosf(ang, &w.y, &w.x);
    float2 cw = w;
    x[1] = cmul(x[1], cw);
#pragma unroll
    for (int j = 2; j < 8; j++) { cw = cmul(cw, w); x[j] = cmul(x[j], cw); }
}

// 512-point FFT core on one line held in smem `ls` (padded i+(i>>3) layout):
// x[] arrives as natural-order stride-64 input; leaves as natural-order output.
__device__ __forceinline__ void fft512_core(float2* x, float2* ls, int t) {
    dft8(x);
    twiddle7(x, 6.283185307179586f * (float)t * (1.0f / 512.0f));
#pragma unroll
    for (int j = 0; j < 8; j++) { int i = 8 * t + j; ls[i + (i >> 3)] = x[j]; }
    __syncthreads();
    {
        const int q = t & 7, p = t >> 3;
#pragma unroll
        for (int r = 0; r < 8; r++) { int i = q + 8 * p + 64 * r; x[r] = ls[i + (i >> 3)]; }
        __syncthreads();
        dft8(x);
        twiddle7(x, 6.283185307179586f * (float)p * (1.0f / 64.0f));
#pragma unroll
        for (int j = 0; j < 8; j++) { int i = q + 64 * p + 8 * j; ls[i + (i >> 3)] = x[j]; }
    }
    __syncthreads();
#pragma unroll
    for (int r = 0; r < 8; r++) { int i = t + 64 * r; x[r] = ls[i + (i >> 3)]; }
    dft8(x);
}

// ---------------------------------------------------------------------------
// Kernel 1: scatter-add, one thread per (sample, coil-PAIR), float4 atomics.
// gridA layout [cg][pix][cl] makes each deposit a single full 16B sector.
// ifftshift folded in as a sign-bit XOR on the weight.
// ---------------------------------------------------------------------------
__global__ void __launch_bounds__(256) scatter_kernel(
    const float* __restrict__ xr, const float* __restrict__ xi,
    const float2* __restrict__ traj, const float* __restrict__ dcf)
{
    int gid = blockIdx.x * blockDim.x + threadIdx.x;   // 0 .. NK*8-1
    int k  = gid & (NK - 1);
    int c2 = gid >> 18;                                // coil pair 0..7
    int c  = 2 * c2;

    float2 t = traj[k];
    int iy = __float2int_rn((t.x + 0.5f) * (float)NN) & (NN - 1);
    int ix = __float2int_rn((t.y + 0.5f) * (float)NN) & (NN - 1);
    float w = __uint_as_float(__float_as_uint(dcf[k]) ^ (((unsigned)(iy + ix) & 1u) << 31));
    int pix = iy * NN + ix;

    float4 v = make_float4(xr[c * NK + k] * w, xi[c * NK + k] * w,
                           xr[(c + 1) * NK + k] * w, xi[(c + 1) * NK + k] * w);

    int cg  = c2 >> 2;
    int cl0 = (c2 & 3) * 2;
    // float2 index -> 16B-aligned (pix*8 and cl0 both even)
    float4* dst = reinterpret_cast<float4*>(&g_bufA[cg * NPIX * 8 + pix * 8 + cl0]);
    atomicAdd(dst, v);
}

// ---------------------------------------------------------------------------
// Kernel 2: row FFTs, interleaved gridA -> per-coil gridB.
// Block = 512 threads = 8 coils (cl = tid&7) x 64 lanes (t = tid>>3), one row.
// grid = (512 rows, 2 coil-groups).
// Load:  gridA[cg][row*NN+e][cl]  -> warp reads 4 x 64B dense chunks.
// Store: gridB[(8cg+cl)][row][e]  -> warp writes 8 planes x 32B full sectors.
// ---------------------------------------------------------------------------
__global__ void __launch_bounds__(512, 2) fft_row_kernel() {
    __shared__ float2 sh[8 * XSTR];
    const int tid = threadIdx.x;
    const int cl  = tid & 7;
    const int t   = tid >> 3;
    const int row = blockIdx.x;
    const int cg  = blockIdx.y;

    const float2* __restrict__ src = g_bufA + cg * NPIX * 8 + row * NN * 8;
    float2*       __restrict__ dst = g_bufB + (cg * 8 + cl) * NPIX + row * NN;
    float2* ls = sh + cl * XSTR;

    float2 x[8];
#pragma unroll
    for (int r = 0; r < 8; r++) x[r] = src[(t + 64 * r) * 8 + cl];

    fft512_core(x, ls, t);

#pragma unroll
    for (int j = 0; j < 8; j++) dst[t + 64 * j] = x[j];
}

// ---------------------------------------------------------------------------
// Kernel 3: fused column FFTs + coil combine, register accumulator,
// __launch_bounds__(512, 2) caps regs at 64 -> 2 blocks/SM, 32 warps/SM.
// Block = 8 columns x 64 lanes, 4 coils per block.
// fftshift folded in as (-1)^(ny+nx) at the atomic store.
// ---------------------------------------------------------------------------
__global__ void __launch_bounds__(512, 2) fft_col_combine_kernel(
    const float* __restrict__ csr, const float* __restrict__ csi,
    float* __restrict__ out)
{
    __shared__ float2 sh[8 * XSTR];
    const int tid  = threadIdx.x;
    const int l0   = blockIdx.x * 8;
    const int c0   = blockIdx.y * 4;
    const int line = tid & 7;
    const int t    = tid >> 3;
    const int col  = l0 + line;

    float2* ls = sh + line * XSTR;
    float2 acc[8];
#pragma unroll
    for (int j = 0; j < 8; j++) acc[j] = make_float2(0.f, 0.f);

    for (int cc = 0; cc < 4; cc++) {
        const int c = c0 + cc;
        const float2* __restrict__ src = g_bufB + c * NPIX;
        const float*  __restrict__ cr  = csr + c * NPIX;
        const float*  __restrict__ ci  = csi + c * NPIX;

        float2 x[8];
#pragma unroll
        for (int r = 0; r < 8; r++) x[r] = src[(t + 64 * r) * NN + col];

        fft512_core(x, ls, t);

#pragma unroll
        for (int j = 0; j < 8; j++) {
            int pix = (t + 64 * j) * NN + col;
            float a = cr[pix], b = ci[pix];
            acc[j].x = fmaf(a, x[j].x, fmaf( b, x[j].y, acc[j].x));
            acc[j].y = fmaf(a, x[j].y, fmaf(-b, x[j].x, acc[j].y));
        }
        __syncthreads();
    }

#pragma unroll
    for (int j = 0; j < 8; j++) {
        int ny  = t + 64 * j;
        int pix = ny * NN + col;
        float sgn = ((ny + col) & 1) ? -1.f : 1.f;
        atomicAdd(&out[pix],        sgn * acc[j].x);
        atomicAdd(&out[NPIX + pix], sgn * acc[j].y);
    }
}

// ---------------------------------------------------------------------------
extern "C" void kernel_launch(void* const* d_in, const int* in_sizes, int n_in,
                              void* d_out, int out_size)
{
    const float* xr   = (const float*)d_in[0];
    const float* xi   = (const float*)d_in[1];
    const float* csr  = (const float*)d_in[2];
    const float* csi  = (const float*)d_in[3];
    const float* traj = (const float*)d_in[4];
    const float* dcf  = (const float*)d_in[5];
    float* out = (float*)d_out;

    void* pA = nullptr;
    cudaGetSymbolAddress(&pA, g_bufA);
    cudaMemsetAsync(pA,  0, (size_t)NC * NPIX * sizeof(float2), 0);
    cudaMemsetAsync(out, 0, (size_t)2 * NPIX * sizeof(float),   0);

    scatter_kernel<<<(NK * 8) / 256, 256>>>(xr, xi, (const float2*)traj, dcf);
    fft_row_kernel<<<dim3(NN, 2), 512>>>();
    fft_col_combine_kernel<<<dim3(NN / 8, NC / 4), 512>>>(csr, csi, out);
}

// round 8
// speedup vs baseline: 1.3135x; 1.3135x over previous
#include <cuda_runtime.h>

#define NN 512
#define NC 16
#define NK 262144            // 2^18
#define NPIX (NN * NN)
#define XSTR 575             // per-line FFT-exchange stride (float2), layout i+(i>>3)

// gridA: coil-interleaved scatter target: [cg][pix][cl], cg=0,1, cl=0..7.
// gridB: per-coil planes [c][row][col] (row-FFT output, col-FFT input).
__device__ __align__(16) float2 g_bufA[NC * NPIX];
__device__ __align__(16) float2 g_bufB[NC * NPIX];

// ---------------------------------------------------------------------------
// complex helpers
// ---------------------------------------------------------------------------
__device__ __forceinline__ float2 cmul(float2 a, float2 b) {
    return make_float2(fmaf(a.x, b.x, -a.y * b.y), fmaf(a.x, b.y, a.y * b.x));
}
__device__ __forceinline__ float2 cadd(float2 a, float2 b) { return make_float2(a.x + b.x, a.y + b.y); }
__device__ __forceinline__ float2 csub(float2 a, float2 b) { return make_float2(a.x - b.x, a.y - b.y); }
__device__ __forceinline__ float2 muli(float2 a) { return make_float2(-a.y, a.x); }  // * (+i)

// 8-point unnormalized inverse DFT (sign +i), in place.
__device__ __forceinline__ void dft8(float2* x) {
    const float C = 0.70710678118654752440f;
    float2 u0 = cadd(x[0], x[4]);
    float2 u1 = csub(x[0], x[4]);
    float2 u2 = cadd(x[1], x[5]);
    float2 d1 = csub(x[1], x[5]);
    float2 u3 = make_float2(C * (d1.x - d1.y), C * (d1.x + d1.y));
    float2 u4 = cadd(x[2], x[6]);
    float2 u5 = muli(csub(x[2], x[6]));
    float2 u6 = cadd(x[3], x[7]);
    float2 d3 = csub(x[3], x[7]);
    float2 u7 = make_float2(-C * (d3.x + d3.y), C * (d3.x - d3.y));
    float2 v0 = cadd(u0, u4);
    float2 v2 = csub(u0, u4);
    float2 v1 = cadd(u1, u5);
    float2 v3 = csub(u1, u5);
    float2 v4 = cadd(u2, u6);
    float2 v6 = muli(csub(u2, u6));
    float2 v5 = cadd(u3, u7);
    float2 v7 = muli(csub(u3, u7));
    x[0] = cadd(v0, v4);
    x[4] = csub(v0, v4);
    x[1] = cadd(v1, v5);
    x[5] = csub(v1, v5);
    x[2] = cadd(v2, v6);
    x[6] = csub(v2, v6);
    x[3] = cadd(v3, v7);
    x[7] = csub(v3, v7);
}

__device__ __forceinline__ void twiddle7(float2* x, float ang) {
    float2 w;
    __sincosf(ang, &w.y, &w.x);
    float2 cw = w;
    x[1] = cmul(x[1], cw);
#pragma unroll
    for (int j = 2; j < 8; j++) { cw = cmul(cw, w); x[j] = cmul(x[j], cw); }
}

// 512-point FFT core on one line held in smem `ls` (padded i+(i>>3) layout):
// x[] arrives as natural-order stride-64 input; leaves as natural-order output.
__device__ __forceinline__ void fft512_core(float2* x, float2* ls, int t) {
    dft8(x);
    twiddle7(x, 6.283185307179586f * (float)t * (1.0f / 512.0f));
#pragma unroll
    for (int j = 0; j < 8; j++) { int i = 8 * t + j; ls[i + (i >> 3)] = x[j]; }
    __syncthreads();
    {
        const int q = t & 7, p = t >> 3;
#pragma unroll
        for (int r = 0; r < 8; r++) { int i = q + 8 * p + 64 * r; x[r] = ls[i + (i >> 3)]; }
        __syncthreads();
        dft8(x);
        twiddle7(x, 6.283185307179586f * (float)p * (1.0f / 64.0f));
#pragma unroll
        for (int j = 0; j < 8; j++) { int i = q + 64 * p + 8 * j; ls[i + (i >> 3)] = x[j]; }
    }
    __syncthreads();
#pragma unroll
    for (int r = 0; r < 8; r++) { int i = t + 64 * r; x[r] = ls[i + (i >> 3)]; }
    dft8(x);
}

// ---------------------------------------------------------------------------
// Kernel 1: scatter-add, one thread per (sample, coil-PAIR), float4 atomics.
// gridA layout [cg][pix][cl] makes each deposit a single full 16B sector.
// ifftshift folded in as a sign-bit XOR on the weight.
// ---------------------------------------------------------------------------
__global__ void __launch_bounds__(256) scatter_kernel(
    const float* __restrict__ xr, const float* __restrict__ xi,
    const float2* __restrict__ traj, const float* __restrict__ dcf)
{
    int gid = blockIdx.x * blockDim.x + threadIdx.x;   // 0 .. NK*8-1
    int k  = gid & (NK - 1);
    int c2 = gid >> 18;                                // coil pair 0..7
    int c  = 2 * c2;

    float2 t = traj[k];
    int iy = __float2int_rn((t.x + 0.5f) * (float)NN) & (NN - 1);
    int ix = __float2int_rn((t.y + 0.5f) * (float)NN) & (NN - 1);
    float w = __uint_as_float(__float_as_uint(dcf[k]) ^ (((unsigned)(iy + ix) & 1u) << 31));
    int pix = iy * NN + ix;

    float4 v = make_float4(xr[c * NK + k] * w, xi[c * NK + k] * w,
                           xr[(c + 1) * NK + k] * w, xi[(c + 1) * NK + k] * w);

    int cg  = c2 >> 2;
    int cl0 = (c2 & 3) * 2;
    float4* dst = reinterpret_cast<float4*>(&g_bufA[cg * NPIX * 8 + pix * 8 + cl0]);
    atomicAdd(dst, v);
}

// ---------------------------------------------------------------------------
// Kernel 2: row FFTs, interleaved gridA -> per-coil gridB.
// Block = 512 threads = 8 coil-lines (line = tid/64, WARP-UNIFORM) x 64 lanes
// (t = tid&63) -> R6's proven conflict-free smem exchange mapping.
// Loads are stride-64B; all 8 coils of the row live in this block, so every
// fetched sector is fully consumed via L1 hits across the block's warps.
// Stores are dense 256B per warp into the per-coil planes.
// ---------------------------------------------------------------------------
__global__ void __launch_bounds__(512, 2) fft_row_kernel() {
    __shared__ float2 sh[8 * XSTR];
    const int tid = threadIdx.x;
    const int cl  = tid >> 6;          // coil line 0..7 (uniform per warp)
    const int t   = tid & 63;
    const int row = blockIdx.x;
    const int cg  = blockIdx.y;

    const float2* __restrict__ src = g_bufA + cg * NPIX * 8 + row * NN * 8;
    float2*       __restrict__ dst = g_bufB + (cg * 8 + cl) * NPIX + row * NN;
    float2* ls = sh + cl * XSTR;

    float2 x[8];
#pragma unroll
    for (int r = 0; r < 8; r++) x[r] = src[(t + 64 * r) * 8 + cl];

    fft512_core(x, ls, t);

#pragma unroll
    for (int j = 0; j < 8; j++) dst[t + 64 * j] = x[j];
}

// ---------------------------------------------------------------------------
// Kernel 3: fused column FFTs + coil combine, register accumulator,
// __launch_bounds__(512, 2) caps regs at 64 -> 2 blocks/SM, 32 warps/SM.
// Block = 8 columns x 64 lanes, 4 coils per block.
// fftshift folded in as (-1)^(ny+nx) at the atomic store.
// ---------------------------------------------------------------------------
__global__ void __launch_bounds__(512, 2) fft_col_combine_kernel(
    const float* __restrict__ csr, const float* __restrict__ csi,
    float* __restrict__ out)
{
    __shared__ float2 sh[8 * XSTR];
    const int tid  = threadIdx.x;
    const int l0   = blockIdx.x * 8;
    const int c0   = blockIdx.y * 4;
    const int line = tid & 7;
    const int t    = tid >> 3;
    const int col  = l0 + line;

    float2* ls = sh + line * XSTR;
    float2 acc[8];
#pragma unroll
    for (int j = 0; j < 8; j++) acc[j] = make_float2(0.f, 0.f);

    for (int cc = 0; cc < 4; cc++) {
        const int c = c0 + cc;
        const float2* __restrict__ src = g_bufB + c * NPIX;
        const float*  __restrict__ cr  = csr + c * NPIX;
        const float*  __restrict__ ci  = csi + c * NPIX;

        float2 x[8];
#pragma unroll
        for (int r = 0; r < 8; r++) x[r] = src[(t + 64 * r) * NN + col];

        fft512_core(x, ls, t);

#pragma unroll
        for (int j = 0; j < 8; j++) {
            int pix = (t + 64 * j) * NN + col;
            float a = cr[pix], b = ci[pix];
            acc[j].x = fmaf(a, x[j].x, fmaf( b, x[j].y, acc[j].x));
            acc[j].y = fmaf(a, x[j].y, fmaf(-b, x[j].x, acc[j].y));
        }
        __syncthreads();
    }

#pragma unroll
    for (int j = 0; j < 8; j++) {
        int ny  = t + 64 * j;
        int pix = ny * NN + col;
        float sgn = ((ny + col) & 1) ? -1.f : 1.f;
        atomicAdd(&out[pix],        sgn * acc[j].x);
        atomicAdd(&out[NPIX + pix], sgn * acc[j].y);
    }
}

// ---------------------------------------------------------------------------
extern "C" void kernel_launch(void* const* d_in, const int* in_sizes, int n_in,
                              void* d_out, int out_size)
{
    const float* xr   = (const float*)d_in[0];
    const float* xi   = (const float*)d_in[1];
    const float* csr  = (const float*)d_in[2];
    const float* csi  = (const float*)d_in[3];
    const float* traj = (const float*)d_in[4];
    const float* dcf  = (const float*)d_in[5];
    float* out = (float*)d_out;

    void* pA = nullptr;
    cudaGetSymbolAddress(&pA, g_bufA);
    cudaMemsetAsync(pA,  0, (size_t)NC * NPIX * sizeof(float2), 0);
    cudaMemsetAsync(out, 0, (size_t)2 * NPIX * sizeof(float),   0);

    scatter_kernel<<<(NK * 8) / 256, 256>>>(xr, xi, (const float2*)traj, dcf);
    fft_row_kernel<<<dim3(NN, 2), 512>>>();
    fft_col_combine_kernel<<<dim3(NN / 8, NC / 4), 512>>>(csr, csi, out);
}

// round 9
// speedup vs baseline: 1.4010x; 1.0667x over previous
#include <cuda_runtime.h>

#define NN 512
#define NC 16
#define NK 262144            // 2^18
#define NPIX (NN * NN)
#define XSTR 575             // per-line FFT-exchange stride (float2), layout i+(i>>3)

// gridA: coil-interleaved scatter target: [cg][pix][cl], cg=0,1, cl=0..7.
// gridB: per-coil planes [c][row][col] (row-FFT output, col-FFT input).
__device__ __align__(16) float2 g_bufA[NC * NPIX];
__device__ __align__(16) float2 g_bufB[NC * NPIX];

// ---------------------------------------------------------------------------
// Fork/join resources, created once at static-init (host-side objects only;
// no device memory is allocated by kernel_launch).
// ---------------------------------------------------------------------------
struct Aux {
    cudaStream_t s1;
    cudaEvent_t evRoot, evJoin;
    Aux() {
        cudaStreamCreateWithFlags(&s1, cudaStreamNonBlocking);
        cudaEventCreateWithFlags(&evRoot, cudaEventDisableTiming);
        cudaEventCreateWithFlags(&evJoin, cudaEventDisableTiming);
    }
};
static Aux g_aux;

// ---------------------------------------------------------------------------
// complex helpers
// ---------------------------------------------------------------------------
__device__ __forceinline__ float2 cmul(float2 a, float2 b) {
    return make_float2(fmaf(a.x, b.x, -a.y * b.y), fmaf(a.x, b.y, a.y * b.x));
}
__device__ __forceinline__ float2 cadd(float2 a, float2 b) { return make_float2(a.x + b.x, a.y + b.y); }
__device__ __forceinline__ float2 csub(float2 a, float2 b) { return make_float2(a.x - b.x, a.y - b.y); }
__device__ __forceinline__ float2 muli(float2 a) { return make_float2(-a.y, a.x); }  // * (+i)

// 8-point unnormalized inverse DFT (sign +i), in place.
__device__ __forceinline__ void dft8(float2* x) {
    const float C = 0.70710678118654752440f;
    float2 u0 = cadd(x[0], x[4]);
    float2 u1 = csub(x[0], x[4]);
    float2 u2 = cadd(x[1], x[5]);
    float2 d1 = csub(x[1], x[5]);
    float2 u3 = make_float2(C * (d1.x - d1.y), C * (d1.x + d1.y));
    float2 u4 = cadd(x[2], x[6]);
    float2 u5 = muli(csub(x[2], x[6]));
    float2 u6 = cadd(x[3], x[7]);
    float2 d3 = csub(x[3], x[7]);
    float2 u7 = make_float2(-C * (d3.x + d3.y), C * (d3.x - d3.y));
    float2 v0 = cadd(u0, u4);
    float2 v2 = csub(u0, u4);
    float2 v1 = cadd(u1, u5);
    float2 v3 = csub(u1, u5);
    float2 v4 = cadd(u2, u6);
    float2 v6 = muli(csub(u2, u6));
    float2 v5 = cadd(u3, u7);
    float2 v7 = muli(csub(u3, u7));
    x[0] = cadd(v0, v4);
    x[4] = csub(v0, v4);
    x[1] = cadd(v1, v5);
    x[5] = csub(v1, v5);
    x[2] = cadd(v2, v6);
    x[6] = csub(v2, v6);
    x[3] = cadd(v3, v7);
    x[7] = csub(v3, v7);
}

// y_j *= w^j, powers built as a depth-3 tree (shorter dep chain than chained mul)
__device__ __forceinline__ void twiddle7(float2* x, float ang) {
    float2 w;
    __sincosf(ang, &w.y, &w.x);
    float2 w2 = cmul(w, w);
    float2 w3 = cmul(w2, w);
    float2 w4 = cmul(w2, w2);
    float2 w5 = cmul(w2, w3);
    float2 w6 = cmul(w3, w3);
    float2 w7 = cmul(w3, w4);
    x[1] = cmul(x[1], w);
    x[2] = cmul(x[2], w2);
    x[3] = cmul(x[3], w3);
    x[4] = cmul(x[4], w4);
    x[5] = cmul(x[5], w5);
    x[6] = cmul(x[6], w6);
    x[7] = cmul(x[7], w7);
}

// 512-point FFT core on one line held in smem `ls` (padded i+(i>>3) layout):
// x[] arrives as natural-order stride-64 input; leaves as natural-order output.
__device__ __forceinline__ void fft512_core(float2* x, float2* ls, int t) {
    dft8(x);
    twiddle7(x, 6.283185307179586f * (float)t * (1.0f / 512.0f));
#pragma unroll
    for (int j = 0; j < 8; j++) { int i = 8 * t + j; ls[i + (i >> 3)] = x[j]; }
    __syncthreads();
    {
        const int q = t & 7, p = t >> 3;
#pragma unroll
        for (int r = 0; r < 8; r++) { int i = q + 8 * p + 64 * r; x[r] = ls[i + (i >> 3)]; }
        __syncthreads();
        dft8(x);
        twiddle7(x, 6.283185307179586f * (float)p * (1.0f / 64.0f));
#pragma unroll
        for (int j = 0; j < 8; j++) { int i = q + 64 * p + 8 * j; ls[i + (i >> 3)] = x[j]; }
    }
    __syncthreads();
#pragma unroll
    for (int r = 0; r < 8; r++) { int i = t + 64 * r; x[r] = ls[i + (i >> 3)]; }
    dft8(x);
}

// ---------------------------------------------------------------------------
// Kernel 1: scatter-add for ONE coil half (8 coils = 4 coil pairs).
// One thread per (sample, coil-pair), single float4 atomic per thread.
// ifftshift folded in as a sign-bit XOR on the weight.
// ---------------------------------------------------------------------------
__global__ void __launch_bounds__(256) scatter_kernel(
    const float* __restrict__ xr, const float* __restrict__ xi,
    const float2* __restrict__ traj, const float* __restrict__ dcf, int cg)
{
    int gid = blockIdx.x * blockDim.x + threadIdx.x;   // 0 .. NK*4-1
    int k   = gid & (NK - 1);
    int c2l = gid >> 18;                               // local coil pair 0..3
    int c   = 2 * (cg * 4 + c2l);

    float2 t = traj[k];
    int iy = __float2int_rn((t.x + 0.5f) * (float)NN) & (NN - 1);
    int ix = __float2int_rn((t.y + 0.5f) * (float)NN) & (NN - 1);
    float w = __uint_as_float(__float_as_uint(dcf[k]) ^ (((unsigned)(iy + ix) & 1u) << 31));
    int pix = iy * NN + ix;

    float4 v = make_float4(xr[c * NK + k] * w, xi[c * NK + k] * w,
                           xr[(c + 1) * NK + k] * w, xi[(c + 1) * NK + k] * w);

    float4* dst = reinterpret_cast<float4*>(&g_bufA[cg * NPIX * 8 + pix * 8 + c2l * 2]);
    atomicAdd(dst, v);
}

// ---------------------------------------------------------------------------
// Kernel 2: row FFTs for ONE coil half, interleaved gridA -> per-coil gridB.
// Block = 512 threads = 8 coil-lines (line = tid/64, warp-uniform) x 64 lanes.
// ---------------------------------------------------------------------------
__global__ void __launch_bounds__(512, 2) fft_row_kernel(int cg) {
    __shared__ float2 sh[8 * XSTR];
    const int tid = threadIdx.x;
    const int cl  = tid >> 6;          // coil line 0..7 (uniform per warp)
    const int t   = tid & 63;
    const int row = blockIdx.x;

    const float2* __restrict__ src = g_bufA + cg * NPIX * 8 + row * NN * 8;
    float2*       __restrict__ dst = g_bufB + (cg * 8 + cl) * NPIX + row * NN;
    float2* ls = sh + cl * XSTR;

    float2 x[8];
#pragma unroll
    for (int r = 0; r < 8; r++) x[r] = src[(t + 64 * r) * 8 + cl];

    fft512_core(x, ls, t);

#pragma unroll
    for (int j = 0; j < 8; j++) dst[t + 64 * j] = x[j];
}

// ---------------------------------------------------------------------------
// Kernel 3: fused column FFTs + coil combine, register accumulator,
// __launch_bounds__(512, 2) caps regs at 64 -> 2 blocks/SM, 32 warps/SM.
// Block = 8 columns x 64 lanes, 4 coils per block.
// fftshift folded in as (-1)^(ny+nx) at the atomic store.
// ---------------------------------------------------------------------------
__global__ void __launch_bounds__(512, 2) fft_col_combine_kernel(
    const float* __restrict__ csr, const float* __restrict__ csi,
    float* __restrict__ out)
{
    __shared__ float2 sh[8 * XSTR];
    const int tid  = threadIdx.x;
    const int l0   = blockIdx.x * 8;
    const int c0   = blockIdx.y * 4;
    const int line = tid & 7;
    const int t    = tid >> 3;
    const int col  = l0 + line;

    float2* ls = sh + line * XSTR;
    float2 acc[8];
#pragma unroll
    for (int j = 0; j < 8; j++) acc[j] = make_float2(0.f, 0.f);

    for (int cc = 0; cc < 4; cc++) {
        const int c = c0 + cc;
        const float2* __restrict__ src = g_bufB + c * NPIX;
        const float*  __restrict__ cr  = csr + c * NPIX;
        const float*  __restrict__ ci  = csi + c * NPIX;

        float2 x[8];
#pragma unroll
        for (int r = 0; r < 8; r++) x[r] = src[(t + 64 * r) * NN + col];

        fft512_core(x, ls, t);

#pragma unroll
        for (int j = 0; j < 8; j++) {
            int pix = (t + 64 * j) * NN + col;
            float a = cr[pix], b = ci[pix];
            acc[j].x = fmaf(a, x[j].x, fmaf( b, x[j].y, acc[j].x));
            acc[j].y = fmaf(a, x[j].y, fmaf(-b, x[j].x, acc[j].y));
        }
        __syncthreads();
    }

#pragma unroll
    for (int j = 0; j < 8; j++) {
        int ny  = t + 64 * j;
        int pix = ny * NN + col;
        float sgn = ((ny + col) & 1) ? -1.f : 1.f;
        atomicAdd(&out[pix],        sgn * acc[j].x);
        atomicAdd(&out[NPIX + pix], sgn * acc[j].y);
    }
}

// ---------------------------------------------------------------------------
extern "C" void kernel_launch(void* const* d_in, const int* in_sizes, int n_in,
                              void* d_out, int out_size)
{
    const float* xr   = (const float*)d_in[0];
    const float* xi   = (const float*)d_in[1];
    const float* csr  = (const float*)d_in[2];
    const float* csi  = (const float*)d_in[3];
    const float* traj = (const float*)d_in[4];
    const float* dcf  = (const float*)d_in[5];
    float* out = (float*)d_out;

    char* pA = nullptr;
    cudaGetSymbolAddress((void**)&pA, g_bufA);
    const size_t halfBytes = (size_t)8 * NPIX * sizeof(float2);   // 16 MB per coil half

    cudaStream_t s0 = 0, s1 = g_aux.s1;

    // out must be zero before the (joined) col+combine kernel
    cudaMemsetAsync(out, 0, (size_t)2 * NPIX * sizeof(float), s0);

    // fork: chain B (coils 8..15) onto s1
    cudaEventRecord(g_aux.evRoot, s0);
    cudaStreamWaitEvent(s1, g_aux.evRoot, 0);

    // chain B on s1
    cudaMemsetAsync(pA + halfBytes, 0, halfBytes, s1);
    scatter_kernel<<<(NK * 4) / 256, 256, 0, s1>>>(xr, xi, (const float2*)traj, dcf, 1);
    fft_row_kernel<<<NN, 512, 0, s1>>>(1);
    cudaEventRecord(g_aux.evJoin, s1);

    // chain A on s0
    cudaMemsetAsync(pA, 0, halfBytes, s0);
    scatter_kernel<<<(NK * 4) / 256, 256, 0, s0>>>(xr, xi, (const float2*)traj, dcf, 0);
    fft_row_kernel<<<NN, 512, 0, s0>>>(0);

    // join, then full-width col FFT + combine
    cudaStreamWaitEvent(s0, g_aux.evJoin, 0);
    fft_col_combine_kernel<<<dim3(NN / 8, NC / 4), 512, 0, s0>>>(csr, csi, out);
}